// round 14
// baseline (speedup 1.0000x reference)
#include <cuda_runtime.h>
#include <cuda_fp16.h>
#include <math.h>

#define BATCH 32
#define T     1024
#define DIM   64
#define NW    8                 // DP strips per batch (128 rows each)
#define NCH   76                // chunks of 16 steps: 1216 steps
#define SPAD  1248              // NCH*16 + 32 FIFO pad
#define HANDW 1220              // handoff row width (halves)
#define SRMAX 221               // epilogue s-rows per tile
#define NSTRIP 256              // strip-persistent producer units (b,w)
#define HAND_BYTES ((NW + 1) * HANDW * 2)     // 21960
#define PROG_OFF   HAND_BYTES
// producer unit: Ah[128][72]h (setup only; reused as Ch[128][34]) | Bh[32][72]h | na[128]f | nb[32]f
#define BH_OFF     18432
#define NA_OFF     23040
#define NB_OFF     23552
#define UNIT_BYTES 24064
#define SMEM_DYN   (3 * UNIT_BYTES)           // 72192

// fp16 cost^2, skew-slotted: g_cst[((b*NW+w)*SPAD + s)*128 + i] holds
// cost[128w+i][s - phi(i)], phi(i) = 6*(i>>2) + (i&3). Invalid = +INF.
__device__ __half g_cst[(size_t)BATCH * NW * SPAD * 128];
__device__ float g_dists[BATCH];
__device__ int   g_flag[BATCH * NW * 32];
__device__ unsigned char g_ihi[224];          // emit table: max i with phi(i)<=sr

__device__ __forceinline__ unsigned hmin2u(unsigned a, unsigned b) {
    __half2 r = __hmin2(*reinterpret_cast<__half2*>(&a), *reinterpret_cast<__half2*>(&b));
    return *reinterpret_cast<unsigned*>(&r);
}
__device__ __forceinline__ unsigned hmax2u(unsigned a, unsigned b) {
    __half2 r = __hmax2(*reinterpret_cast<__half2*>(&a), *reinterpret_cast<__half2*>(&b));
    return *reinterpret_cast<unsigned*>(&r);
}
__device__ __forceinline__ int ld_acq_gpu(const int* p) {
    int v; asm volatile("ld.acquire.gpu.s32 %0, [%1];" : "=r"(v) : "l"(p) : "memory");
    return v;
}

#define UBAR(id) asm volatile("bar.sync %0, %1;" :: "r"(id), "r"(128) : "memory")

#define LDMX4(r0, r1, r2, r3, addr)                                            \
    asm volatile("ldmatrix.sync.aligned.m8n8.x4.shared.b16 {%0,%1,%2,%3}, [%4];" \
                 : "=r"(r0), "=r"(r1), "=r"(r2), "=r"(r3) : "r"(addr))

#define MMA16816(c, a, bb0, bb1)                                               \
    asm volatile("mma.sync.aligned.m16n8k16.row.col.f32.f16.f16.f32 "          \
                 "{%0,%1,%2,%3},{%4,%5,%6,%7},{%8,%9},{%0,%1,%2,%3};"          \
                 : "+f"((c)[0]), "+f"((c)[1]), "+f"((c)[2]), "+f"((c)[3])      \
                 : "r"((a)[0]), "r"((a)[1]), "r"((a)[2]), "r"((a)[3]),         \
                   "r"(bb0), "r"(bb1))

// ---------------------------------------------------------------------------
// fill: INF boundary slots; zero flags; emit table.
// ---------------------------------------------------------------------------
__global__ __launch_bounds__(256) void fill_kernel() {
    int cta = blockIdx.x;                       // 256 CTAs, one per (b,w)
    unsigned* p32 = (unsigned*)(g_cst + (size_t)cta * SPAD * 128);
    const int NS = 189 + (SPAD - 1024);
    for (int v = threadIdx.x; v < NS * 64; v += 256) {
        int sr = v >> 6, q = v & 63;
        int s = (sr < 189) ? sr : (1024 + sr - 189);
        p32[(size_t)s * 64 + q] = 0x7C007C00u;
    }
    int fi = cta * 256 + threadIdx.x;
    if (fi < BATCH * NW * 32) g_flag[fi] = 0;
    if (cta == 1 && threadIdx.x < 224) {
        int sr = threadIdx.x;
        int aq = sr / 6, bq = sr - 6 * aq;
        int ihi = 4 * aq + (bq < 3 ? bq : 3);
        g_ihi[sr] = (unsigned char)(ihi > 127 ? 127 : ihi);
    }
}

// ---------------------------------------------------------------------------
// Strip-persistent producer: unit owns strip (b, w). A tile loaded/converted
// once, ldmatrix fragments hoisted to registers; then 32 jt tiles produced
// in DP-consumption order. Release via bar + single-thread st.release.gpu.
// ---------------------------------------------------------------------------
__device__ void producer_part(const float* __restrict__ A, const float* __restrict__ B,
                              char* __restrict__ base, int barid, int unit, int t128) {
    __half* Ah  = (__half*)base;                 // [128][72] (setup only)
    __half* Bh  = (__half*)(base + BH_OFF);      // [32][72]
    float* na_s = (float*)(base + NA_OFF);       // [128]
    float* nb_s = (float*)(base + NB_OFF);       // [32]
    const int b = unit >> 3, w = unit & 7;
    const int wq = t128 >> 5, l = t128 & 31;
    const int r0 = t128 >> 4, kq = t128 & 15;
    const unsigned sBase = (unsigned)__cvta_generic_to_shared(base);
    const unsigned sAh = sBase, sBh = sBase + BH_OFF;

    const int m0 = 32 * wq;
    const unsigned ahAddr = sAh + (unsigned)(((m0 + (l & 15)) * 72 + (l >> 4) * 8) * 2);
    const unsigned bhAddr = sBh + (unsigned)((((l & 15)) * 72 + (l >> 4) * 8) * 2);

    // ---- strip setup: A tile load + convert + norms, fragments to regs ----
    {
        const float4* Ar = (const float4*)(A + ((size_t)b * T + w * 128) * DIM);
#pragma unroll
        for (int it = 0; it < 16; it++) {
            int row = r0 + it * 8;
            float4 x = Ar[row * 16 + kq];
            float part = x.x * x.x + x.y * x.y + x.z * x.z + x.w * x.w;
            part += __shfl_xor_sync(0xffffffffu, part, 1);
            part += __shfl_xor_sync(0xffffffffu, part, 2);
            part += __shfl_xor_sync(0xffffffffu, part, 4);
            part += __shfl_xor_sync(0xffffffffu, part, 8);
            if (kq == 0) na_s[row] = part;
            __half2 h0 = __floats2half2_rn(x.x, x.y);
            __half2 h1 = __floats2half2_rn(x.z, x.w);
            uint2 u; u.x = *(unsigned*)&h0; u.y = *(unsigned*)&h1;
            *(uint2*)(Ah + row * 72 + kq * 4) = u;
        }
    }
    UBAR(barid);
    unsigned afA[4][4], afB[4][4];               // A fragments, rows m0/m0+16
#pragma unroll
    for (int kk = 0; kk < 4; kk++) {
        LDMX4(afA[kk][0], afA[kk][1], afA[kk][2], afA[kk][3], ahAddr + kk * 32);
        LDMX4(afB[kk][0], afB[kk][1], afB[kk][2], afB[kk][3], ahAddr + 2304 + kk * 32);
    }
    // (Ah smem is dead after the bar in the first jt iteration; Ch aliases it)

    const size_t strip = (size_t)(b * NW + w);
    const int fbase = (int)strip * 32;
    __half* Ch = (__half*)base;                  // [128][34]

    for (int jt = 0; jt < 32; jt++) {
        int j0 = jt * 32;
        // B tile: coalesced load + convert + norms
        {
            const float4* Br = (const float4*)(B + ((size_t)b * T + j0) * DIM);
#pragma unroll
            for (int it = 0; it < 4; it++) {
                int row = r0 + it * 8;
                float4 x = Br[row * 16 + kq];
                float part = x.x * x.x + x.y * x.y + x.z * x.z + x.w * x.w;
                part += __shfl_xor_sync(0xffffffffu, part, 1);
                part += __shfl_xor_sync(0xffffffffu, part, 2);
                part += __shfl_xor_sync(0xffffffffu, part, 4);
                part += __shfl_xor_sync(0xffffffffu, part, 8);
                if (kq == 0) nb_s[row] = part;
                __half2 h0 = __floats2half2_rn(x.x, x.y);
                __half2 h1 = __floats2half2_rn(x.z, x.w);
                uint2 u; u.x = *(unsigned*)&h0; u.y = *(unsigned*)&h1;
                *(uint2*)(Bh + row * 72 + kq * 4) = u;
            }
        }
        UBAR(barid);                             // bar1: B ready (A frags in regs)

        float acc[2][4][4];
#pragma unroll
        for (int mi = 0; mi < 2; mi++)
#pragma unroll
            for (int nj = 0; nj < 4; nj++)
#pragma unroll
                for (int q = 0; q < 4; q++) acc[mi][nj][q] = 0.f;

#pragma unroll
        for (int kk = 0; kk < 4; kk++) {
            unsigned b0[4], b1[4];
            LDMX4(b0[0], b0[1], b0[2], b0[3], bhAddr + kk * 32);
            LDMX4(b1[0], b1[1], b1[2], b1[3], bhAddr + 2304 + kk * 32);
            MMA16816(acc[0][0], afA[kk], b0[0], b0[2]);
            MMA16816(acc[0][1], afA[kk], b0[1], b0[3]);
            MMA16816(acc[0][2], afA[kk], b1[0], b1[2]);
            MMA16816(acc[0][3], afA[kk], b1[1], b1[3]);
            MMA16816(acc[1][0], afB[kk], b0[0], b0[2]);
            MMA16816(acc[1][1], afB[kk], b0[1], b0[3]);
            MMA16816(acc[1][2], afB[kk], b1[0], b1[2]);
            MMA16816(acc[1][3], afB[kk], b1[1], b1[3]);
        }

        // epilogue: cost^2 -> fp16 into Ch (own warp's 32 rows)
        {
            const int cb = 2 * (l & 3);
#pragma unroll
            for (int mi = 0; mi < 2; mi++) {
                int r = m0 + 16 * mi + (l >> 2);
                float na0 = na_s[r], na8 = na_s[r + 8];
#pragma unroll
                for (int nj = 0; nj < 4; nj++) {
                    int c0 = 8 * nj + cb;
                    float nb0 = nb_s[c0], nb1 = nb_s[c0 + 1];
                    float s00 = fmaxf(na0 + nb0 - 2.f * acc[mi][nj][0], 1e-12f);
                    float s01 = fmaxf(na0 + nb1 - 2.f * acc[mi][nj][1], 1e-12f);
                    float s10 = fmaxf(na8 + nb0 - 2.f * acc[mi][nj][2], 1e-12f);
                    float s11 = fmaxf(na8 + nb1 - 2.f * acc[mi][nj][3], 1e-12f);
                    __half2 h0 = __floats2half2_rn(s00, s01);
                    __half2 h1 = __floats2half2_rn(s10, s11);
                    *(unsigned*)&Ch[r * 34 + c0] = *(unsigned*)&h0;
                    *(unsigned*)&Ch[(r + 8) * 34 + c0] = *(unsigned*)&h1;
                }
            }
        }
        UBAR(barid);                             // bar2: Ch complete, Bh free

        // Table-driven skewed emit: slot s = j + phi(i); sr = s - j0.
        size_t sbase = (strip * SPAD + j0) * 128;
#pragma unroll 1
        for (int it = 0; it < 56; it++) {
            int sr = it * 4 + wq;
            if (sr < SRMAX) {
                int ihi = __ldg(&g_ihi[sr]);
                int i = ihi - 31 + l;
                int jr = sr - (6 * (i >> 2) + (i & 3));
                if (i >= 0 && jr >= 0 && jr < 32)
                    g_cst[sbase + (size_t)sr * 128 + i] = Ch[i * 34 + jr];
            }
        }
        UBAR(barid);                             // bar3: emit done (hb for release)
        if (t128 == 0)
            asm volatile("st.release.gpu.s32 [%0], %1;"
                         :: "l"(&g_flag[fbase + jt]), "r"(1) : "memory");
    }
}

// ---------------------------------------------------------------------------
// DP part: sole occupant of its CTA/SM. E=2-skew systolic engine; chunks
// gated on cumulative tile flags. (Proven engine, unchanged.)
// ---------------------------------------------------------------------------
__device__ void dp_part(int b, char* smem) {
    unsigned short* hand = (unsigned short*)smem;
    int* progress = (int*)(smem + PROG_OFF);
    const int tid = threadIdx.x, w = tid >> 5, lane = tid & 31;

    for (int v = tid; v < (NW + 1) * HANDW / 2; v += 256)
        ((unsigned*)hand)[v] = 0x7C007C00u;
    if (lane == 0) progress[w] = 0;
    asm volatile("bar.sync 5, 256;" ::: "memory");

    const unsigned short* hrow = &hand[((w == 0) ? NW : (w - 1)) * HANDW];
    unsigned wrow;   // smem addr; +s*2 -> hand[w][s-189]
    {
        unsigned base;
        asm("{ .reg .u64 t; cvta.to.shared.u64 t, %1; cvt.u32.u64 %0, t; }"
            : "=r"(base) : "l"(&hand[w * HANDW]));
        wrow = base - 378u;
    }

    const int fbase = (b * NW + w) * 32;
    int done = 0;
    while (ld_acq_gpu(&g_flag[fbase]) == 0) __nanosleep(128);
    done = 1;

    const __half* cp = g_cst + (size_t)(b * NW + w) * SPAD * 128 + lane * 4;
    uint2 fA[16], fB[16];
#pragma unroll
    for (int q = 0; q < 16; q++) fA[q] = *(const uint2*)(cp + (size_t)q * 128);
#pragma unroll
    for (int q = 0; q < 16; q++) fB[q] = *(const uint2*)(cp + (size_t)(16 + q) * 128);

    const unsigned INF2 = 0x7C007C00u;
    unsigned A = INF2, B = INF2, upAp = INF2, upBp = INF2;
    unsigned sh0 = INF2, sh1 = INF2;
    unsigned hv0 = INF2, hv1 = INF2, hv2 = INF2;
    const bool isl0 = (lane == 0);
    const bool fix0 = (w == 0) && isl0;
    const unsigned p31 = (lane == 31) ? 1u : 0u;
    const __half* cq = cp;

#define DP_STEP(kk, F, ROFF, FIRST)                                            \
    {                                                                          \
        const int s = sbase + (kk);                                            \
        uint2 cw = F[kk];                                                      \
        F[kk] = *(const uint2*)(cq + (size_t)((kk) + (ROFF)) * 128);           \
        unsigned shu = isl0 ? hv0 : sh0;                                       \
        unsigned upA = __byte_perm(shu, A, 0x5432);                            \
        unsigned upB = __byte_perm(A, B, 0x5432);                              \
        unsigned nA = hmax2u(cw.x, hmin2u(hmin2u(upA, upAp), A));              \
        unsigned nB = hmax2u(cw.y, hmin2u(hmin2u(upB, upBp), B));              \
        if ((FIRST) && (kk) == 0) {                                            \
            if (fix0) nA = (nA & 0xFFFF0000u) | (cw.x & 0xFFFFu);              \
        }                                                                      \
        unsigned pr = p31 & (unsigned)(s >= 189);                              \
        asm volatile(                                                          \
            "{ .reg .pred p; setp.ne.u32 p, %0, 0; @p st.shared.u16 [%1], %2; }" \
            :: "r"(pr), "r"(wrow + (unsigned)s * 2),                           \
               "h"((unsigned short)(nB >> 16)));                               \
        unsigned shn = __shfl_up_sync(0xffffffffu, B, 1);                      \
        sh0 = sh1; sh1 = shn;                                                  \
        upAp = upA; upBp = upB;                                                \
        A = nA; B = nB;                                                        \
        hv0 = hv1; hv1 = hv2;                                                  \
        hv2 = ((unsigned)hrow[s + 3]) << 16;                                   \
    }

    for (int td = 0; td < NCH / 2; td++) {
        {   // gate: chunk td refills read slots <= 32*td+63 -> tiles <= td+1
            int need = td + 2; if (need > 32) need = 32;
            while (done < need) {
                if (ld_acq_gpu(&g_flag[fbase + done]) != 0) done++;
                else __nanosleep(64);
            }
        }
        if (w) {
            int need = 2 * td + 14; if (need > NCH) need = NCH;
            while (((volatile int*)progress)[w - 1] < need) __nanosleep(32);
            __threadfence_block();
        }
        if (td == 0) {
            hv0 = ((unsigned)hrow[0]) << 16;
            hv1 = ((unsigned)hrow[1]) << 16;
            hv2 = ((unsigned)hrow[2]) << 16;
        }
        {
            const int sbase = 32 * td;
#pragma unroll
            for (int kk = 0; kk < 16; kk++) DP_STEP(kk, fA, 32, (td == 0))
        }
        __syncwarp();
        __threadfence_block();
        if (lane == 0) ((volatile int*)progress)[w] = 2 * td + 1;
        {
            const int sbase = 32 * td + 16;
#pragma unroll
            for (int kk = 0; kk < 16; kk++) DP_STEP(kk, fB, 48, false)
        }
        __syncwarp();
        __threadfence_block();
        if (lane == 0) ((volatile int*)progress)[w] = 2 * td + 2;
        cq += 32 * 128;
    }
#undef DP_STEP

    asm volatile("bar.sync 5, 256;" ::: "memory");
    if (tid == 0)
        g_dists[b] = sqrtf(__half2float(__ushort_as_half(hand[7 * HANDW + 1023])));
}

// ---------------------------------------------------------------------------
// Fused persistent kernel, 148 CTAs (all wave-1 resident).
//   CTA 0..31:  DP warps only (batch = blockIdx).
//   CTA 32..147: up to 3 strip-persistent producer units (256 active).
// ---------------------------------------------------------------------------
__global__ void __launch_bounds__(384, 1) fused_kernel(const float* __restrict__ A,
                                                       const float* __restrict__ B) {
    extern __shared__ char smem[];
    const int cta = blockIdx.x, tid = threadIdx.x;
    if (cta < BATCH) {
        if (tid < 256) dp_part(cta, smem);
        return;
    }
    int ul = tid >> 7;
    int unit = (cta - BATCH) * 3 + ul;
    if (unit < NSTRIP)
        producer_part(A, B, smem + ul * UNIT_BYTES, 1 + ul, unit, tid & 127);
}

// ---------------------------------------------------------------------------
__global__ void finish_kernel(float* __restrict__ out) {
    int t = threadIdx.x;
    float v = g_dists[t];
#pragma unroll
    for (int o = 16; o; o >>= 1) v += __shfl_xor_sync(0xffffffffu, v, o);
    if (t == 0) out[0] = v * (1.0f / BATCH);
}

extern "C" void kernel_launch(void* const* d_in, const int* in_sizes, int n_in,
                              void* d_out, int out_size) {
    const float* pred = (const float*)d_in[0];
    const float* targ = (const float*)d_in[1];
    cudaFuncSetAttribute(fused_kernel, cudaFuncAttributeMaxDynamicSharedMemorySize, SMEM_DYN);
    fill_kernel<<<BATCH * NW, 256>>>();
    fused_kernel<<<148, 384, SMEM_DYN>>>(pred, targ);
    finish_kernel<<<1, 32>>>((float*)d_out);
}

// round 15
// speedup vs baseline: 1.9293x; 1.9293x over previous
#include <cuda_runtime.h>
#include <cuda_fp16.h>
#include <math.h>

#define BATCH 32
#define T     1024
#define DIM   64
#define NW    8                 // DP strips per batch (128 rows each)
#define NCH   76                // chunks of 16 steps: 1216 steps
#define SPAD  1248              // NCH*16 + 32 FIFO pad
#define HANDW 1220              // handoff row width (halves)
#define SRMAX 221               // epilogue s-rows per tile
#define NUNITS 464              // producer units: 116 CTAs * 4
#define NTILES 8192             // 32 b * 8 w * 32 jt
#define HAND_BYTES ((NW + 1) * HANDW * 2)     // 21960
#define PROG_OFF   HAND_BYTES
// producer unit: Ah[128][72]h (reused as Ch[128][34]) | Bh[32][72]h | na[128]f | nb[32]f
#define BH_OFF     18432
#define NA_OFF     23040
#define NB_OFF     23552
#define UNIT_BYTES 24064
#define SMEM_DYN   (4 * UNIT_BYTES)           // 96256

// fp16 cost^2, skew-slotted: g_cst[((b*NW+w)*SPAD + s)*128 + i] holds
// cost[128w+i][s - phi(i)], phi(i) = 6*(i>>2) + (i&3). Invalid = +INF.
__device__ __half g_cst[(size_t)BATCH * NW * SPAD * 128];
__device__ float g_dists[BATCH];
__device__ int   g_done;
__device__ int   g_flag[BATCH * NW * 32];
__device__ unsigned char g_pairs[256];
__device__ unsigned char g_ihi[224];          // emit table: max i with phi(i)<=sr

__device__ __forceinline__ unsigned hmin2u(unsigned a, unsigned b) {
    __half2 r = __hmin2(*reinterpret_cast<__half2*>(&a), *reinterpret_cast<__half2*>(&b));
    return *reinterpret_cast<unsigned*>(&r);
}
__device__ __forceinline__ unsigned hmax2u(unsigned a, unsigned b) {
    __half2 r = __hmax2(*reinterpret_cast<__half2*>(&a), *reinterpret_cast<__half2*>(&b));
    return *reinterpret_cast<unsigned*>(&r);
}
__device__ __forceinline__ int ld_acq_gpu(const int* p) {
    int v; asm volatile("ld.acquire.gpu.s32 %0, [%1];" : "=r"(v) : "l"(p) : "memory");
    return v;
}

#define UBAR(id) asm volatile("bar.sync %0, %1;" :: "r"(id), "r"(128) : "memory")

#define LDMX4(r0, r1, r2, r3, addr)                                            \
    asm volatile("ldmatrix.sync.aligned.m8n8.x4.shared.b16 {%0,%1,%2,%3}, [%4];" \
                 : "=r"(r0), "=r"(r1), "=r"(r2), "=r"(r3) : "r"(addr))

#define MMA16816(c, a, bb0, bb1)                                               \
    asm volatile("mma.sync.aligned.m16n8k16.row.col.f32.f16.f16.f32 "          \
                 "{%0,%1,%2,%3},{%4,%5,%6,%7},{%8,%9},{%0,%1,%2,%3};"          \
                 : "+f"((c)[0]), "+f"((c)[1]), "+f"((c)[2]), "+f"((c)[3])      \
                 : "r"((a)[0]), "r"((a)[1]), "r"((a)[2]), "r"((a)[3]),         \
                   "r"(bb0), "r"(bb1))

// ---------------------------------------------------------------------------
// fill: INF boundary slots (512 CTAs, 2 per strip); zero flags; tables; g_done.
// ---------------------------------------------------------------------------
__global__ __launch_bounds__(256) void fill_kernel() {
    int cta = blockIdx.x;
    int strip = cta >> 1, half = cta & 1;
    unsigned* p32 = (unsigned*)(g_cst + (size_t)strip * SPAD * 128);
    const int NS = 189 + (SPAD - 1024);          // 413 slots
    int lo = half ? 207 : 0, hi = half ? NS : 207;
    for (int v = lo * 64 + threadIdx.x; v < hi * 64; v += 256) {
        int sr = v >> 6, q = v & 63;
        int s = (sr < 189) ? sr : (1024 + sr - 189);
        p32[(size_t)s * 64 + q] = 0x7C007C00u;
    }
    if (half == 0 && threadIdx.x < 32) g_flag[strip * 32 + threadIdx.x] = 0;
    if (cta == 0 && threadIdx.x == 0) {
        int idx = 0;
        for (int m = 0; m <= 80; m++)
            for (int w = 0; w < 8; w++) {
                int jt = m - 7 * w;
                if (jt >= 0 && jt < 32) g_pairs[idx++] = (unsigned char)(w * 32 + jt);
            }
        g_done = 0;
    }
    if (cta == 1 && threadIdx.x < 224) {
        int sr = threadIdx.x;
        int aq = sr / 6, bq = sr - 6 * aq;
        int ihi = 4 * aq + (bq < 3 ? bq : 3);
        g_ihi[sr] = (unsigned char)(ihi > 127 ? 127 : ihi);
    }
}

// ---------------------------------------------------------------------------
// Producer unit: 128 threads, fp16 tensor-core GEMM (m16n8k16), 128x32 tile,
// priority (DP-consumption) tile order. Release = bar + st.release.gpu.
// ---------------------------------------------------------------------------
__device__ void producer_part(const float* __restrict__ A, const float* __restrict__ B,
                              char* __restrict__ base, int barid, int unit, int t128) {
    __half* Ah  = (__half*)base;                 // [128][72]
    __half* Bh  = (__half*)(base + BH_OFF);      // [32][72]
    float* na_s = (float*)(base + NA_OFF);       // [128]
    float* nb_s = (float*)(base + NB_OFF);       // [32]
    const int wq = t128 >> 5, l = t128 & 31;
    const int r0 = t128 >> 4, kq = t128 & 15;
    const unsigned sBase = (unsigned)__cvta_generic_to_shared(base);
    const unsigned sAh = sBase, sBh = sBase + BH_OFF;

    const int m0 = 32 * wq;
    const unsigned ahAddr = sAh + (unsigned)(((m0 + (l & 15)) * 72 + (l >> 4) * 8) * 2);
    const unsigned bhAddr = sBh + (unsigned)((((l & 15)) * 72 + (l >> 4) * 8) * 2);

    for (int p = unit; p < NTILES; p += NUNITS) {
        int pr = g_pairs[p >> 5];
        int b = p & 31, w = pr >> 5, jt = pr & 31;
        int j0 = jt * 32;

        // A tile: coalesced (warp = 512B contiguous), norm via shfl width-16
        {
            const float4* Ar = (const float4*)(A + ((size_t)b * T + w * 128) * DIM);
#pragma unroll
            for (int it = 0; it < 16; it++) {
                int row = r0 + it * 8;
                float4 x = Ar[row * 16 + kq];
                float part = x.x * x.x + x.y * x.y + x.z * x.z + x.w * x.w;
                part += __shfl_xor_sync(0xffffffffu, part, 1);
                part += __shfl_xor_sync(0xffffffffu, part, 2);
                part += __shfl_xor_sync(0xffffffffu, part, 4);
                part += __shfl_xor_sync(0xffffffffu, part, 8);
                if (kq == 0) na_s[row] = part;
                __half2 h0 = __floats2half2_rn(x.x, x.y);
                __half2 h1 = __floats2half2_rn(x.z, x.w);
                uint2 u; u.x = *(unsigned*)&h0; u.y = *(unsigned*)&h1;
                *(uint2*)(Ah + row * 72 + kq * 4) = u;
            }
        }
        // B tile: same pattern, 4 iterations
        {
            const float4* Br = (const float4*)(B + ((size_t)b * T + j0) * DIM);
#pragma unroll
            for (int it = 0; it < 4; it++) {
                int row = r0 + it * 8;
                float4 x = Br[row * 16 + kq];
                float part = x.x * x.x + x.y * x.y + x.z * x.z + x.w * x.w;
                part += __shfl_xor_sync(0xffffffffu, part, 1);
                part += __shfl_xor_sync(0xffffffffu, part, 2);
                part += __shfl_xor_sync(0xffffffffu, part, 4);
                part += __shfl_xor_sync(0xffffffffu, part, 8);
                if (kq == 0) nb_s[row] = part;
                __half2 h0 = __floats2half2_rn(x.x, x.y);
                __half2 h1 = __floats2half2_rn(x.z, x.w);
                uint2 u; u.x = *(unsigned*)&h0; u.y = *(unsigned*)&h1;
                *(uint2*)(Bh + row * 72 + kq * 4) = u;
            }
        }
        UBAR(barid);

        float acc[2][4][4];
#pragma unroll
        for (int mi = 0; mi < 2; mi++)
#pragma unroll
            for (int nj = 0; nj < 4; nj++)
#pragma unroll
                for (int q = 0; q < 4; q++) acc[mi][nj][q] = 0.f;

#pragma unroll
        for (int kk = 0; kk < 4; kk++) {
            unsigned a0[4], a1[4], b0[4], b1[4];
            LDMX4(a0[0], a0[1], a0[2], a0[3], ahAddr + kk * 32);
            LDMX4(a1[0], a1[1], a1[2], a1[3], ahAddr + 2304 + kk * 32);
            LDMX4(b0[0], b0[1], b0[2], b0[3], bhAddr + kk * 32);
            LDMX4(b1[0], b1[1], b1[2], b1[3], bhAddr + 2304 + kk * 32);
            MMA16816(acc[0][0], a0, b0[0], b0[2]);
            MMA16816(acc[0][1], a0, b0[1], b0[3]);
            MMA16816(acc[0][2], a0, b1[0], b1[2]);
            MMA16816(acc[0][3], a0, b1[1], b1[3]);
            MMA16816(acc[1][0], a1, b0[0], b0[2]);
            MMA16816(acc[1][1], a1, b0[1], b0[3]);
            MMA16816(acc[1][2], a1, b1[0], b1[2]);
            MMA16816(acc[1][3], a1, b1[1], b1[3]);
        }
        UBAR(barid);                 // Ah reads done; reuse as Ch

        __half* Ch = (__half*)base;  // [128][34]
        {
            const int cb = 2 * (l & 3);
#pragma unroll
            for (int mi = 0; mi < 2; mi++) {
                int r = m0 + 16 * mi + (l >> 2);
                float na0 = na_s[r], na8 = na_s[r + 8];
#pragma unroll
                for (int nj = 0; nj < 4; nj++) {
                    int c0 = 8 * nj + cb;
                    float nb0 = nb_s[c0], nb1 = nb_s[c0 + 1];
                    float s00 = fmaxf(na0 + nb0 - 2.f * acc[mi][nj][0], 1e-12f);
                    float s01 = fmaxf(na0 + nb1 - 2.f * acc[mi][nj][1], 1e-12f);
                    float s10 = fmaxf(na8 + nb0 - 2.f * acc[mi][nj][2], 1e-12f);
                    float s11 = fmaxf(na8 + nb1 - 2.f * acc[mi][nj][3], 1e-12f);
                    __half2 h0 = __floats2half2_rn(s00, s01);
                    __half2 h1 = __floats2half2_rn(s10, s11);
                    *(unsigned*)&Ch[r * 34 + c0] = *(unsigned*)&h0;
                    *(unsigned*)&Ch[(r + 8) * 34 + c0] = *(unsigned*)&h1;
                }
            }
        }
        UBAR(barid);

        // Table-driven skewed emit: slot s = j + phi(i); sr = s - j0.
        size_t sbase = ((size_t)(b * NW + w) * SPAD + j0) * 128;
#pragma unroll 4
        for (int it = 0; it < 56; it++) {
            int sr = it * 4 + wq;
            if (sr < SRMAX) {
                int ihi = __ldg(&g_ihi[sr]);
                int i = ihi - 31 + l;
                int jr = sr - (6 * (i >> 2) + (i & 3));
                if (i >= 0 && jr >= 0 && jr < 32)
                    g_cst[sbase + (size_t)sr * 128 + i] = Ch[i * 34 + jr];
            }
        }
        UBAR(barid);                 // hb: all emit STGs ordered before release
        if (t128 == 0)
            asm volatile("st.release.gpu.s32 [%0], %1;"
                         :: "l"(&g_flag[(b * NW + w) * 32 + jt]), "r"(1) : "memory");
    }
}

// ---------------------------------------------------------------------------
// DP part: sole occupant of its CTA/SM. E=2-skew systolic engine; chunks
// gated on cumulative tile flags. Last CTA reduces the mean (merged finish).
// ---------------------------------------------------------------------------
__device__ void dp_part(int b, char* smem, float* __restrict__ out) {
    unsigned short* hand = (unsigned short*)smem;
    int* progress = (int*)(smem + PROG_OFF);
    const int tid = threadIdx.x, w = tid >> 5, lane = tid & 31;

    for (int v = tid; v < (NW + 1) * HANDW / 2; v += 256)
        ((unsigned*)hand)[v] = 0x7C007C00u;
    if (lane == 0) progress[w] = 0;
    asm volatile("bar.sync 5, 256;" ::: "memory");

    const unsigned short* hrow = &hand[((w == 0) ? NW : (w - 1)) * HANDW];
    unsigned wrow;   // smem addr; +s*2 -> hand[w][s-189]
    {
        unsigned base;
        asm("{ .reg .u64 t; cvta.to.shared.u64 t, %1; cvt.u32.u64 %0, t; }"
            : "=r"(base) : "l"(&hand[w * HANDW]));
        wrow = base - 378u;
    }

    const int fbase = (b * NW + w) * 32;
    int done = 0;
    while (ld_acq_gpu(&g_flag[fbase]) == 0) __nanosleep(128);
    done = 1;

    const __half* cp = g_cst + (size_t)(b * NW + w) * SPAD * 128 + lane * 4;
    uint2 fA[16], fB[16];
#pragma unroll
    for (int q = 0; q < 16; q++) fA[q] = *(const uint2*)(cp + (size_t)q * 128);
#pragma unroll
    for (int q = 0; q < 16; q++) fB[q] = *(const uint2*)(cp + (size_t)(16 + q) * 128);

    const unsigned INF2 = 0x7C007C00u;
    unsigned A = INF2, B = INF2, upAp = INF2, upBp = INF2;
    unsigned sh0 = INF2, sh1 = INF2;
    unsigned hv0 = INF2, hv1 = INF2, hv2 = INF2;
    const bool isl0 = (lane == 0);
    const bool fix0 = (w == 0) && isl0;
    const unsigned p31 = (lane == 31) ? 1u : 0u;
    const __half* cq = cp;

#define DP_STEP(kk, F, ROFF, FIRST)                                            \
    {                                                                          \
        const int s = sbase + (kk);                                            \
        uint2 cw = F[kk];                                                      \
        F[kk] = *(const uint2*)(cq + (size_t)((kk) + (ROFF)) * 128);           \
        unsigned shu = isl0 ? hv0 : sh0;                                       \
        unsigned upA = __byte_perm(shu, A, 0x5432);                            \
        unsigned upB = __byte_perm(A, B, 0x5432);                              \
        unsigned nA = hmax2u(cw.x, hmin2u(hmin2u(upA, upAp), A));              \
        unsigned nB = hmax2u(cw.y, hmin2u(hmin2u(upB, upBp), B));              \
        if ((FIRST) && (kk) == 0) {                                            \
            if (fix0) nA = (nA & 0xFFFF0000u) | (cw.x & 0xFFFFu);              \
        }                                                                      \
        unsigned pr = p31 & (unsigned)(s >= 189);                              \
        asm volatile(                                                          \
            "{ .reg .pred p; setp.ne.u32 p, %0, 0; @p st.shared.u16 [%1], %2; }" \
            :: "r"(pr), "r"(wrow + (unsigned)s * 2),                           \
               "h"((unsigned short)(nB >> 16)));                               \
        unsigned shn = __shfl_up_sync(0xffffffffu, B, 1);                      \
        sh0 = sh1; sh1 = shn;                                                  \
        upAp = upA; upBp = upB;                                                \
        A = nA; B = nB;                                                        \
        hv0 = hv1; hv1 = hv2;                                                  \
        hv2 = ((unsigned)hrow[s + 3]) << 16;                                   \
    }

    for (int td = 0; td < NCH / 2; td++) {
        {   // gate: chunk td refills read slots <= 32*td+63 -> tiles <= td+1
            int need = td + 2; if (need > 32) need = 32;
            while (done < need) {
                if (ld_acq_gpu(&g_flag[fbase + done]) != 0) done++;
                else __nanosleep(64);
            }
        }
        if (w) {
            int need = 2 * td + 14; if (need > NCH) need = NCH;
            while (((volatile int*)progress)[w - 1] < need) __nanosleep(32);
            __threadfence_block();
        }
        if (td == 0) {
            hv0 = ((unsigned)hrow[0]) << 16;
            hv1 = ((unsigned)hrow[1]) << 16;
            hv2 = ((unsigned)hrow[2]) << 16;
        }
        {
            const int sbase = 32 * td;
#pragma unroll
            for (int kk = 0; kk < 16; kk++) DP_STEP(kk, fA, 32, (td == 0))
        }
        __syncwarp();
        __threadfence_block();
        if (lane == 0) ((volatile int*)progress)[w] = 2 * td + 1;
        {
            const int sbase = 32 * td + 16;
#pragma unroll
            for (int kk = 0; kk < 16; kk++) DP_STEP(kk, fB, 48, false)
        }
        __syncwarp();
        __threadfence_block();
        if (lane == 0) ((volatile int*)progress)[w] = 2 * td + 2;
        cq += 32 * 128;
    }
#undef DP_STEP

    asm volatile("bar.sync 5, 256;" ::: "memory");
    if (tid == 0) {
        g_dists[b] = sqrtf(__half2float(__ushort_as_half(hand[7 * HANDW + 1023])));
        __threadfence();
        int old = atomicAdd(&g_done, 1);
        if (old == BATCH - 1) {                    // last CTA reduces (merged finish)
            __threadfence();
            float s = 0.f;
#pragma unroll
            for (int i = 0; i < BATCH; i++) s += ((volatile float*)g_dists)[i];
            out[0] = s * (1.0f / BATCH);
        }
    }
}

// ---------------------------------------------------------------------------
// Fused persistent kernel, 148 CTAs (all wave-1 resident), 512 threads.
//   CTA 0..31:  DP warps only (batch = blockIdx; tids 256+ exit).
//   CTA 32..147: 4 tensor-core producer units each (464 total).
// ---------------------------------------------------------------------------
__global__ void __launch_bounds__(512, 1) fused_kernel(const float* __restrict__ A,
                                                       const float* __restrict__ B,
                                                       float* __restrict__ out) {
    extern __shared__ char smem[];
    const int cta = blockIdx.x, tid = threadIdx.x;
    if (cta < BATCH) {
        if (tid < 256) dp_part(cta, smem, out);
        return;
    }
    int ul = tid >> 7;
    producer_part(A, B, smem + ul * UNIT_BYTES, 1 + ul,
                  (cta - BATCH) * 4 + ul, tid & 127);
}

extern "C" void kernel_launch(void* const* d_in, const int* in_sizes, int n_in,
                              void* d_out, int out_size) {
    const float* pred = (const float*)d_in[0];
    const float* targ = (const float*)d_in[1];
    cudaFuncSetAttribute(fused_kernel, cudaFuncAttributeMaxDynamicSharedMemorySize, SMEM_DYN);
    fill_kernel<<<512, 256>>>();
    fused_kernel<<<148, 512, SMEM_DYN>>>(pred, targ, (float*)d_out);
}